// round 14
// baseline (speedup 1.0000x reference)
#include <cuda_runtime.h>
#include <cuda_fp16.h>
#include <math.h>
#include <stdint.h>

#define NB 4
#define NT 8192
#define NC 64
#define NS 256
#define NV 256
#define NL 30
#define NTOK (NB*NT)

// ---------------- device scratch ---------------------------------------------
__device__ __half g_xh[(size_t)(NL+1)*NTOK*NC];
__device__ __half g_gates[(size_t)NL*NTOK*NC];   // [l][tok][64]
__device__ __half g_convw[NL*128*128];
__device__ __half g_resw[NL*64*64];
__device__ __half g_skipw[NL*256*64];
__device__ __half g_w0t[256*256];
__device__ __half g_w1t[256*256];
__device__ float g_skipb[NS];
__device__ float g_num;
__device__ int   g_cnt;
__device__ int   g_flags[256];

// ---------------- helpers ------------------------------------------------------
__device__ __forceinline__ uint32_t s2u(const void* p){
  uint32_t a;
  asm("{ .reg .u64 t; cvta.to.shared.u64 t, %1; cvt.u32.u64 %0, t; }" : "=r"(a) : "l"(p));
  return a;
}
__device__ __forceinline__ void mma16816(float* c, uint32_t a0, uint32_t a1,
                                         uint32_t a2, uint32_t a3,
                                         uint32_t b0, uint32_t b1){
  asm volatile("mma.sync.aligned.m16n8k16.row.col.f32.f16.f16.f32 "
    "{%0,%1,%2,%3}, {%4,%5,%6,%7}, {%8,%9}, {%0,%1,%2,%3};"
    : "+f"(c[0]), "+f"(c[1]), "+f"(c[2]), "+f"(c[3])
    : "r"(a0), "r"(a1), "r"(a2), "r"(a3), "r"(b0), "r"(b1));
}
__device__ __forceinline__ void mma16816h(uint32_t* c, uint32_t a0, uint32_t a1,
                                          uint32_t a2, uint32_t a3,
                                          uint32_t b0, uint32_t b1){
  asm volatile("mma.sync.aligned.m16n8k16.row.col.f16.f16.f16.f16 "
    "{%0,%1}, {%2,%3,%4,%5}, {%6,%7}, {%0,%1};"
    : "+r"(c[0]), "+r"(c[1])
    : "r"(a0), "r"(a1), "r"(a2), "r"(a3), "r"(b0), "r"(b1));
}
__device__ __forceinline__ void ldsm4(uint32_t* r, uint32_t a){
  asm volatile("ldmatrix.sync.aligned.m8n8.x4.shared.b16 {%0,%1,%2,%3}, [%4];"
    : "=r"(r[0]), "=r"(r[1]), "=r"(r[2]), "=r"(r[3]) : "r"(a));
}
__device__ __forceinline__ void cp16(uint32_t d, const void* s){
  asm volatile("cp.async.ca.shared.global [%0], [%1], 16;" :: "r"(d), "l"(s));
}
__device__ __forceinline__ void cp16g(uint32_t d, const void* s){
  asm volatile("cp.async.cg.shared.global [%0], [%1], 16;" :: "r"(d), "l"(s));
}
__device__ __forceinline__ void cp16zg(uint32_t d, const void* s, int pred){
  asm volatile("{\n .reg .pred p;\n setp.ne.b32 p, %2, 0;\n"
    " @p  cp.async.cg.shared.global [%0], [%1], 16;\n"
    " @!p cp.async.cg.shared.global [%0], [%1], 16, 0;\n}"
    :: "r"(d), "l"(s), "r"(pred));
}
#define CP_COMMIT() asm volatile("cp.async.commit_group;" ::: "memory")
#define CP_WAIT0()  asm volatile("cp.async.wait_group 0;" ::: "memory")
#define CP_WAIT1()  asm volatile("cp.async.wait_group 1;" ::: "memory")

__device__ __forceinline__ uint32_t pack2(float a, float b){
  __half2 t = __floats2half2_rn(a, b);
  return *(uint32_t*)&t;
}
__device__ __forceinline__ float tanh_ap(float x){
  float r;
  asm("tanh.approx.f32 %0, %1;" : "=f"(r) : "f"(x));
  return r;
}
__device__ __forceinline__ int ld_acq(const int* p){
  int v;
  asm volatile("ld.acquire.gpu.global.b32 %0, [%1];" : "=r"(v) : "l"(p) : "memory");
  return v;
}
__device__ __forceinline__ void red_rel(int* p){
  asm volatile("red.release.gpu.global.add.s32 [%0], %1;" :: "l"(p), "r"(1) : "memory");
}

// ---------------- merged prep (weights + embed + misc in one launch) -------------
#define PREPW_CTAS 4832
#define EMBED_CTAS (NTOK/4)

__global__ void prep_all_kernel(const int* __restrict__ wf,
                                const float* __restrict__ emb,
                                const float* __restrict__ conv_w,
                                const float* __restrict__ res_w,
                                const float* __restrict__ skip_w,
                                const float* __restrict__ w0,
                                const float* __restrict__ w1,
                                const float* __restrict__ skip_b){
  int blk = blockIdx.x;
  if (blk < PREPW_CTAS){
    int idx = blk*256 + threadIdx.x;
    if (idx < NL*128*128){
      int k = idx & 127, f = (idx>>7)&127, l = idx>>14;
      float v = (k < 64) ? conv_w[((l*2+1)*64 + k)*128 + f]
                         : conv_w[((l*2+0)*64 + (k-64))*128 + f];
      g_convw[((size_t)l*128 + f)*128 + k] = __float2half(v);
      return;
    }
    idx -= NL*128*128;
    if (idx < NL*64*64){
      int k = idx & 63, o = (idx>>6)&63, l = idx>>12;
      g_resw[((size_t)l*64 + o)*64 + k] = __float2half(res_w[((size_t)l*64 + k)*64 + o]);
      return;
    }
    idx -= NL*64*64;
    if (idx < NL*256*64){
      int k = idx & 63, v2 = (idx>>6)&255, l = idx>>14;
      g_skipw[((size_t)l*256 + v2)*64 + k] = __float2half(skip_w[((size_t)l*64 + k)*256 + v2]);
      return;
    }
    idx -= NL*256*64;
    if (idx < 256*256){
      int k = idx & 255, v2 = idx>>8;
      g_w0t[v2*256 + k] = __float2half(w0[k*256 + v2]);
      return;
    }
    idx -= 256*256;
    if (idx < 256*256){
      int k = idx & 255, v2 = idx>>8;
      g_w1t[v2*256 + k] = __float2half(w1[k*256 + v2]);
    }
    return;
  }
  blk -= PREPW_CTAS;
  if (blk < EMBED_CTAS){
    int tid = threadIdx.x;
    int tok = blk*4 + (tid >> 6);
    int c   = tid & 63;
    int t   = tok & (NT-1);
    int lab = (t == 0) ? 128 : wf[tok-1];
    g_xh[(size_t)tok*NC + c] = __float2half(emb[lab*NC + c]);
    return;
  }
  // last block: misc
  int s = threadIdx.x;
  if (s < 256){
    float a = 0.f;
    #pragma unroll 6
    for (int l = 0; l < NL; l++) a += skip_b[l*NS + s];
    g_skipb[s] = a;
    g_flags[s] = 0;
    if (s == 0){ g_num = 0.f; g_cnt = 0; }
  }
}

// ---------------- fused 30-layer kernel (unchanged from R12) ----------------------
#define LOFF_A  1536
#define LOFF_W  36352
#define LOFF_R  71168
#define LOFF_G  80384
#define LSMEM   98816
#define APITCH  272
#define RPITCH  144

__device__ __forceinline__ void stage_w(uint32_t sbase, int l, int buf, int tid,
                                        const float* conv_b, const float* res_b){
  if (tid < 32) cp16(sbase + buf*768 + tid*16, (const char*)(conv_b + l*128) + tid*16);
  else if (tid < 48) cp16(sbase + buf*768 + 512 + (tid-32)*16,
                          (const char*)(res_b + l*64) + (tid-32)*16);
  const char* wsrc = (const char*)(g_convw + (size_t)l*16384);
  #pragma unroll
  for (int i = 0; i < 8; i++){
    int idx = tid + i*256, row = idx >> 4, c = idx & 15;
    cp16(sbase + LOFF_W + row*APITCH + c*16, wsrc + row*256 + c*16);
  }
}

__device__ __forceinline__ void stage_r(uint32_t sbase, int l, int tid){
  const char* rsrc = (const char*)(g_resw + (size_t)l*4096);
  #pragma unroll
  for (int i = 0; i < 2; i++){
    int idx = tid + i*256, row = idx >> 3, c = idx & 7;
    cp16(sbase + LOFF_R + row*RPITCH + c*16, rsrc + row*128 + c*16);
  }
}

__device__ __forceinline__ void stage_ashift(uint32_t sbase, const __half* xsrc,
                                             int dL, int tok0, int tid){
  #pragma unroll
  for (int i = 0; i < 4; i++){
    int idx = tid + i*256;
    int row = idx >> 3, c = idx & 7;
    int tok = tok0 + row, t = tok & (NT-1);
    cp16zg(sbase + LOFF_A + row*APITCH + 128 + c*16,
           (const char*)(xsrc + (long)(tok - dL)*64) + c*16, t >= dL);
  }
}

__global__ __launch_bounds__(256, 2) void layers_kernel(
    const float* __restrict__ conv_b, const float* __restrict__ res_b)
{
  extern __shared__ char sm[];
  uint32_t sbase = s2u(sm);
  const int tid = threadIdx.x, warp = tid >> 5, lane = tid & 31;
  const int l4 = lane >> 2, q = lane & 3;
  const int cta = blockIdx.x;
  const int tok0 = cta * 128;

  stage_w(sbase, 0, 0, tid, conv_b, res_b);
  stage_r(sbase, 0, tid);
  {
    const char* xs = (const char*)(g_xh + (size_t)tok0*64);
    #pragma unroll
    for (int i = 0; i < 4; i++){
      int idx = tid + i*256, row = idx >> 3, c = idx & 7;
      cp16g(sbase + LOFF_A + row*APITCH + c*16, xs + row*128 + c*16);
    }
    #pragma unroll
    for (int i = 0; i < 4; i++){
      int idx = tid + i*256, row = idx >> 3, c = idx & 7;
      int tok = tok0 + row, t = tok & (NT-1);
      cp16zg(sbase + LOFF_A + row*APITCH + 128 + c*16,
             (const char*)(g_xh + (long)(tok - 1)*64) + c*16, t >= 1);
    }
  }
  CP_COMMIT();

  const uint32_t aAddr = sbase + LOFF_A + (warp*16 + (lane & 15))*APITCH + ((lane >> 4) << 4);
  const uint32_t bAddr = sbase + LOFF_W + ((lane & 7) + ((lane >> 4) << 3))*APITCH
                       + (((lane >> 3) & 1) << 4);
  const uint32_t rAddr = sbase + LOFF_R + ((lane & 7) + ((lane >> 4) << 3))*RPITCH
                       + (((lane >> 3) & 1) << 4);

  for (int l = 0; l < NL; l++){
    const int buf = l & 1;
    CP_WAIT0();
    __syncthreads();

    uint32_t hacc[16][2];
    #pragma unroll
    for (int j = 0; j < 16; j++){ hacc[j][0]=0; hacc[j][1]=0; }
    #pragma unroll
    for (int s = 0; s < 8; s++){
      uint32_t A[4];
      ldsm4(A, aAddr + s*32);
      #pragma unroll
      for (int p = 0; p < 8; p++){
        uint32_t Bv[4];
        ldsm4(Bv, bAddr + p*16*APITCH + s*32);
        mma16816h(hacc[2*p],   A[0], A[1], A[2], A[3], Bv[0], Bv[1]);
        mma16816h(hacc[2*p+1], A[0], A[1], A[2], A[3], Bv[2], Bv[3]);
      }
    }

    const float* sCB = (const float*)(sm + buf*768);
    uint32_t G[8][2];
    #pragma unroll
    for (int j = 0; j < 8; j++){
      int c0 = j*8 + q*2;
      float b1c = sCB[c0], b2c = sCB[c0+1], b1s = sCB[64+c0], b2s = sCB[64+c0+1];
      #pragma unroll
      for (int r = 0; r < 2; r++){
        float2 f1 = __half22float2(*(__half2*)&hacc[j][r]);
        float2 f2 = __half22float2(*(__half2*)&hacc[j+8][r]);
        float h1a = f1.x + b1c;
        float h1b = f1.y + b2c;
        float h2a = f2.x + b1s;
        float h2b = f2.y + b2s;
        float ga = tanh_ap(h1a) * fmaf(0.5f, tanh_ap(0.5f*h2a), 0.5f);
        float gb = tanh_ap(h1b) * fmaf(0.5f, tanh_ap(0.5f*h2b), 0.5f);
        G[j][r] = pack2(ga, gb);
      }
    }

    float r2[8][4];
    #pragma unroll
    for (int j = 0; j < 8; j++){ r2[j][0]=0; r2[j][1]=0; r2[j][2]=0; r2[j][3]=0; }
    #pragma unroll
    for (int s = 0; s < 4; s++){
      uint32_t a0 = G[2*s][0], a1 = G[2*s][1], a2 = G[2*s+1][0], a3 = G[2*s+1][1];
      #pragma unroll
      for (int p = 0; p < 4; p++){
        uint32_t Bv[4];
        ldsm4(Bv, rAddr + p*16*RPITCH + s*32);
        mma16816(r2[2*p],   a0, a1, a2, a3, Bv[0], Bv[1]);
        mma16816(r2[2*p+1], a0, a1, a2, a3, Bv[2], Bv[3]);
      }
    }

    {
      const float* sRB = (const float*)(sm + buf*768 + 512);
      char* aRow = sm + LOFF_A + (warp*16)*APITCH;
      char* gRow = sm + LOFF_G + (warp*16)*RPITCH;
      #pragma unroll
      for (int j = 0; j < 8; j++){
        int c0 = j*8 + q*2;
        float rb0 = sRB[c0], rb1 = sRB[c0+1];
        #pragma unroll
        for (int r = 0; r < 2; r++){
          int row = l4 + 8*r;
          uint32_t xp = *(const uint32_t*)(aRow + row*APITCH + j*16 + q*4);
          float2 xb = __half22float2(*(__half2*)&xp);
          float o0 = xb.x + r2[j][2*r]   + rb0;
          float o1 = xb.y + r2[j][2*r+1] + rb1;
          *(uint32_t*)(aRow + row*APITCH + j*16 + q*4) = pack2(o0, o1);
          *(uint32_t*)(gRow + row*RPITCH + j*16 + q*4) = G[j][r];
        }
      }
    }
    __syncthreads();

    {
      char* gd = (char*)(g_gates + ((size_t)l*NTOK + tok0)*64);
      #pragma unroll
      for (int i = 0; i < 4; i++){
        int idx = tid + i*256, row = idx >> 3, c = idx & 7;
        *(uint4*)(gd + row*128 + c*16) = *(uint4*)(sm + LOFF_G + row*RPITCH + c*16);
      }
    }
    if (l < NL-1){
      char* xo = (char*)(g_xh + (size_t)(l+1)*NTOK*NC + (size_t)tok0*NC);
      #pragma unroll
      for (int i = 0; i < 4; i++){
        int idx = tid + i*256, row = idx >> 3, c = idx & 7;
        *(uint4*)(xo + row*128 + c*16) = *(uint4*)(sm + LOFF_A + row*APITCH + c*16);
      }
      stage_w(sbase, l+1, buf ^ 1, tid, conv_b, res_b);
      CP_COMMIT();
      __syncthreads();

      if (tid == 0) red_rel(g_flags + cta);
      {
        const int dnext = 1 << ((l+1) % 10);
        if (tid == 0){
          int step = dnext >> 7; if (step == 0) step = 1;
          int nb = cta - step;
          if (nb >= 0){
            while (ld_acq(g_flags + nb) < l + 1) __nanosleep(32);
          }
        }
        __syncthreads();
        stage_ashift(sbase, g_xh + (size_t)(l+1)*NTOK*NC, dnext, tok0, tid);
        stage_r(sbase, l+1, tid);
        CP_COMMIT();
      }
    }
  }
}

// ---------------- head kernel: 64 tok/CTA, 2 CTA/SM, grid 512 --------------------
// smem: skb@0 b0@1024 b1@2048; ring 2 x (G 64x144=9216 + WC 256x144=36864) @3072
//       after phase1: S 64x528 @3072 (33792); W2A @36864 (36864); W2B @73728 (36864);
//       comb @110592 (2048) -> HSMEM 112640
#define HOFF_SKB 0
#define HOFF_B0  1024
#define HOFF_B1  2048
#define HRING    3072
#define HSLOT    46080
#define SPITCH   528
#define HS_S     3072
#define HS_W2A   36864
#define HS_W2B   73728
#define HS_CMB   110592
#define HSMEM    112640

__device__ __forceinline__ void head_stage1(uint32_t sbase, int slot, int l,
                                            int tok0, int tid){
  uint32_t gOff = HRING + slot*HSLOT;
  uint32_t wOff = gOff + 64*RPITCH;
  const char* gs = (const char*)(g_gates + ((size_t)l*NTOK + tok0)*64);
  #pragma unroll
  for (int i = 0; i < 2; i++){
    int idx = tid + i*256, row = idx >> 3, c = idx & 7;
    cp16(sbase + gOff + row*RPITCH + c*16, gs + row*128 + c*16);
  }
  const char* ws = (const char*)(g_skipw + (size_t)l*16384);
  #pragma unroll
  for (int i = 0; i < 8; i++){
    int idx = tid + i*256, row = idx >> 3, c = idx & 7;
    cp16(sbase + wOff + row*RPITCH + c*16, ws + row*128 + c*16);
  }
  CP_COMMIT();
}

// stage one 64-wide K chunk of a 256x256 weight (rows v=0..255, cols c*64..)
__device__ __forceinline__ void stage_w2c(uint32_t sbase, uint32_t bufOff,
                                          const __half* wt, int c, int tid){
  const char* ws = (const char*)wt;
  #pragma unroll
  for (int i = 0; i < 8; i++){
    int idx = tid + i*256, row = idx >> 3, cc = idx & 7;
    cp16(sbase + bufOff + row*RPITCH + cc*16, ws + row*512 + c*128 + cc*16);
  }
  CP_COMMIT();
}

__global__ __launch_bounds__(256, 2) void head_kernel(
    const float* __restrict__ b0, const float* __restrict__ b1,
    const int* __restrict__ wf, const int* __restrict__ lens,
    float* __restrict__ out)
{
  extern __shared__ char sm[];
  uint32_t sbase = s2u(sm);
  const int tid = threadIdx.x, warp = tid >> 5, lane = tid & 31;
  const int l4 = lane >> 2, q = lane & 3;
  const int g = warp >> 1, h = warp & 1;   // token-group (16 tok), col-half (128)
  const int tok0 = blockIdx.x * 64;

  float* sSKB = (float*)(sm + HOFF_SKB);
  float* sB0  = (float*)(sm + HOFF_B0);
  float* sB1  = (float*)(sm + HOFF_B1);
  sSKB[tid] = g_skipb[tid];
  sB0[tid]  = b0[tid];
  sB1[tid]  = b1[tid];

  head_stage1(sbase, 0, 0, tok0, tid);
  head_stage1(sbase, 1, 1, tok0, tid);

  float acc[16][4];
  #pragma unroll
  for (int j = 0; j < 16; j++){ acc[j][0]=0; acc[j][1]=0; acc[j][2]=0; acc[j][3]=0; }

  const uint32_t aLane  = (g*16 + (lane & 15))*RPITCH + ((lane >> 4) << 4);
  const uint32_t bLane  = (h*128 + (lane & 7) + ((lane >> 4) << 3))*RPITCH + (((lane >> 3) & 1) << 4);
  const uint32_t aLaneS = (g*16 + (lane & 15))*SPITCH + ((lane >> 4) << 4);

  // ---- phase 1: skip_sum (K=1920), 2-slot ring ----
  for (int l = 0; l < NL; l++){
    const int slot = l & 1;
    if (l < NL-1) CP_WAIT1(); else CP_WAIT0();
    __syncthreads();

    uint32_t aAddr = sbase + HRING + slot*HSLOT + aLane;
    uint32_t bAddr = sbase + HRING + slot*HSLOT + 64*RPITCH + bLane;
    #pragma unroll
    for (int s = 0; s < 4; s++){
      uint32_t A[4];
      ldsm4(A, aAddr + s*32);
      #pragma unroll
      for (int p = 0; p < 8; p++){
        uint32_t Bv[4];
        ldsm4(Bv, bAddr + p*16*RPITCH + s*32);
        mma16816(acc[2*p],   A[0], A[1], A[2], A[3], Bv[0], Bv[1]);
        mma16816(acc[2*p+1], A[0], A[1], A[2], A[3], Bv[2], Bv[3]);
      }
    }
    __syncthreads();
    if (l + 2 < NL) head_stage1(sbase, slot, l + 2, tok0, tid);
  }

  // ---- write S = skip_sum + skipb; prefetch first two W2 chunks ----
  stage_w2c(sbase, HS_W2A, g_w0t, 0, tid);
  stage_w2c(sbase, HS_W2B, g_w0t, 1, tid);
  #pragma unroll
  for (int j = 0; j < 16; j++){
    int c0 = h*128 + j*8 + q*2;
    float s0 = sSKB[c0], s1 = sSKB[c0+1];
    int row = g*16 + l4;
    uint32_t col = h*256 + j*16 + q*4;
    *(uint32_t*)(sm + HS_S + row*SPITCH + col)     = pack2(acc[j][0]+s0, acc[j][1]+s1);
    *(uint32_t*)(sm + HS_S + (row+8)*SPITCH + col) = pack2(acc[j][2]+s0, acc[j][3]+s1);
  }
  #pragma unroll
  for (int j = 0; j < 16; j++){ acc[j][0]=0; acc[j][1]=0; acc[j][2]=0; acc[j][3]=0; }
  CP_WAIT1();
  __syncthreads();   // S visible + W2A ready

  // ---- phases 2+3: 8 pipelined K=64 chunks (0-3: w0, 4-7: w1) ----
  #pragma unroll 1
  for (int c = 0; c < 8; c++){
    if (c > 0){
      if (c < 7) CP_WAIT1(); else CP_WAIT0();
      __syncthreads();
    }
    uint32_t wbase = sbase + ((c & 1) ? HS_W2B : HS_W2A) + bLane;
    uint32_t aBase = sbase + HS_S + aLaneS + (c & 3)*128;
    #pragma unroll
    for (int s = 0; s < 4; s++){
      uint32_t A[4];
      ldsm4(A, aBase + s*32);
      #pragma unroll
      for (int p = 0; p < 8; p++){
        uint32_t Bv[4];
        ldsm4(Bv, wbase + p*16*RPITCH + s*32);
        mma16816(acc[2*p],   A[0], A[1], A[2], A[3], Bv[0], Bv[1]);
        mma16816(acc[2*p+1], A[0], A[1], A[2], A[3], Bv[2], Bv[3]);
      }
    }
    __syncthreads();
    if (c + 2 < 8){
      int nc = c + 2;
      stage_w2c(sbase, (nc & 1) ? HS_W2B : HS_W2A,
                (nc < 4) ? g_w0t : g_w1t, nc & 3, tid);
    }
    if (c == 3){
      // hid = relu(acc + b0) -> S (published by next iteration's syncthreads)
      #pragma unroll
      for (int j = 0; j < 16; j++){
        int c0 = h*128 + j*8 + q*2;
        float s0 = sB0[c0], s1 = sB0[c0+1];
        int row = g*16 + l4;
        uint32_t col = h*256 + j*16 + q*4;
        *(uint32_t*)(sm + HS_S + row*SPITCH + col) =
            pack2(fmaxf(acc[j][0]+s0, 0.f), fmaxf(acc[j][1]+s1, 0.f));
        *(uint32_t*)(sm + HS_S + (row+8)*SPITCH + col) =
            pack2(fmaxf(acc[j][2]+s0, 0.f), fmaxf(acc[j][3]+s1, 0.f));
      }
      #pragma unroll
      for (int j = 0; j < 16; j++){ acc[j][0]=0; acc[j][1]=0; acc[j][2]=0; acc[j][3]=0; }
    }
  }

  // ---- CE stage 1: per-warp partial over its 128-col half ----
  #pragma unroll
  for (int r = 0; r < 2; r++){
    int tokl = g*16 + l4 + 8*r;
    int lab = wf[tok0 + tokl];
    float mx = -1e30f;
    #pragma unroll
    for (int j = 0; j < 16; j++){
      int c0 = h*128 + j*8 + q*2;
      float v0 = acc[j][2*r]   + sB1[c0];
      float v1 = acc[j][2*r+1] + sB1[c0+1];
      mx = fmaxf(mx, fmaxf(v0, v1));
    }
    mx = fmaxf(mx, __shfl_xor_sync(0xffffffffu, mx, 1));
    mx = fmaxf(mx, __shfl_xor_sync(0xffffffffu, mx, 2));
    float ss = 0.f, lv = 0.f;
    #pragma unroll
    for (int j = 0; j < 16; j++){
      int c0 = h*128 + j*8 + q*2;
      float v0 = acc[j][2*r]   + sB1[c0];
      float v1 = acc[j][2*r+1] + sB1[c0+1];
      ss += __expf(v0 - mx) + __expf(v1 - mx);
      if (lab == c0)   lv += v0;
      if (lab == c0+1) lv += v1;
    }
    ss += __shfl_xor_sync(0xffffffffu, ss, 1);
    ss += __shfl_xor_sync(0xffffffffu, ss, 2);
    lv += __shfl_xor_sync(0xffffffffu, lv, 1);
    lv += __shfl_xor_sync(0xffffffffu, lv, 2);
    if (q == 0)
      *(float4*)(sm + HS_CMB + (h*64 + tokl)*16) = make_float4(mx, ss, lv, 0.f);
  }
  __syncthreads();

  // ---- CE stage 2: merge halves (h==0 warps, lanes 0..15) ----
  if (h == 0){
    float val = 0.f;
    if (lane < 16){
      int tokl = g*16 + lane;
      float4 c0v = *(float4*)(sm + HS_CMB + tokl*16);
      float4 c1v = *(float4*)(sm + HS_CMB + (64 + tokl)*16);
      float mm = fmaxf(c0v.x, c1v.x);
      float ss = c0v.y*__expf(c0v.x - mm) + c1v.y*__expf(c1v.x - mm);
      float lv = c0v.z + c1v.z;
      float ce = mm + logf(ss) - lv;
      int gt = tok0 + tokl;
      int t = gt & (NT-1);
      int b = gt >> 13;
      if (t < lens[b]) val = ce;
    }
    #pragma unroll
    for (int off = 16; off; off >>= 1)
      val += __shfl_xor_sync(0xffffffffu, val, off);
    if (lane == 0) atomicAdd(&g_num, val);
  }

  // ---- fused finalize ----
  __syncthreads();
  if (tid == 0){
    __threadfence();
    if (atomicAdd(&g_cnt, 1) == gridDim.x - 1){
      float num = atomicAdd(&g_num, 0.f);
      float denom = 0.f;
      for (int b = 0; b < NB; b++) denom += (float)lens[b];
      out[0] = num / fmaxf(denom, 1.f);
    }
  }
}

// ---------------- launcher ----------------------------------------------------------
extern "C" void kernel_launch(void* const* d_in, const int* in_sizes, int n_in,
                              void* d_out, int out_size)
{
  const int*   wf     = (const int*)d_in[0];
  const int*   lens   = (const int*)d_in[1];
  const float* emb    = (const float*)d_in[2];
  const float* conv_w = (const float*)d_in[3];
  const float* conv_b = (const float*)d_in[4];
  const float* res_w  = (const float*)d_in[5];
  const float* res_b  = (const float*)d_in[6];
  const float* skip_w = (const float*)d_in[7];
  const float* skip_b = (const float*)d_in[8];
  const float* w0     = (const float*)d_in[9];
  const float* b0     = (const float*)d_in[10];
  const float* w1     = (const float*)d_in[11];
  const float* b1     = (const float*)d_in[12];

  cudaFuncSetAttribute(layers_kernel, cudaFuncAttributeMaxDynamicSharedMemorySize, LSMEM);
  cudaFuncSetAttribute(head_kernel,   cudaFuncAttributeMaxDynamicSharedMemorySize, HSMEM);

  prep_all_kernel<<<PREPW_CTAS + EMBED_CTAS + 1, 256>>>(wf, emb, conv_w, res_w,
                                                        skip_w, w0, w1, skip_b);
  layers_kernel<<<NTOK/128, 256, LSMEM>>>(conv_b, res_b);
  head_kernel<<<NTOK/64, 256, HSMEM>>>(b0, b1, wf, lens, (float*)d_out);
}

// round 15
// speedup vs baseline: 1.1637x; 1.1637x over previous
#include <cuda_runtime.h>
#include <cuda_fp16.h>
#include <math.h>
#include <stdint.h>

#define NB 4
#define NT 8192
#define NC 64
#define NS 256
#define NV 256
#define NL 30
#define NTOK (NB*NT)

// ---------------- device scratch ---------------------------------------------
__device__ __half g_xh[(size_t)(NL+1)*NTOK*NC];
__device__ __half g_gates[(size_t)NL*NTOK*NC];   // [l][tok][64]
__device__ __half g_convw[NL*128*128];
__device__ __half g_resw[NL*64*64];
__device__ __half g_skipw[NL*256*64];
__device__ __half g_w0t[256*256];
__device__ __half g_w1t[256*256];
__device__ float g_skipb[NS];
__device__ float g_num;
__device__ int   g_cnt;
__device__ int   g_flags[256];

// ---------------- helpers ------------------------------------------------------
__device__ __forceinline__ uint32_t s2u(const void* p){
  uint32_t a;
  asm("{ .reg .u64 t; cvta.to.shared.u64 t, %1; cvt.u32.u64 %0, t; }" : "=r"(a) : "l"(p));
  return a;
}
__device__ __forceinline__ void mma16816(float* c, uint32_t a0, uint32_t a1,
                                         uint32_t a2, uint32_t a3,
                                         uint32_t b0, uint32_t b1){
  asm volatile("mma.sync.aligned.m16n8k16.row.col.f32.f16.f16.f32 "
    "{%0,%1,%2,%3}, {%4,%5,%6,%7}, {%8,%9}, {%0,%1,%2,%3};"
    : "+f"(c[0]), "+f"(c[1]), "+f"(c[2]), "+f"(c[3])
    : "r"(a0), "r"(a1), "r"(a2), "r"(a3), "r"(b0), "r"(b1));
}
__device__ __forceinline__ void mma16816h(uint32_t* c, uint32_t a0, uint32_t a1,
                                          uint32_t a2, uint32_t a3,
                                          uint32_t b0, uint32_t b1){
  asm volatile("mma.sync.aligned.m16n8k16.row.col.f16.f16.f16.f16 "
    "{%0,%1}, {%2,%3,%4,%5}, {%6,%7}, {%0,%1};"
    : "+r"(c[0]), "+r"(c[1])
    : "r"(a0), "r"(a1), "r"(a2), "r"(a3), "r"(b0), "r"(b1));
}
__device__ __forceinline__ void ldsm4(uint32_t* r, uint32_t a){
  asm volatile("ldmatrix.sync.aligned.m8n8.x4.shared.b16 {%0,%1,%2,%3}, [%4];"
    : "=r"(r[0]), "=r"(r[1]), "=r"(r[2]), "=r"(r[3]) : "r"(a));
}
__device__ __forceinline__ void cp16(uint32_t d, const void* s){
  asm volatile("cp.async.ca.shared.global [%0], [%1], 16;" :: "r"(d), "l"(s));
}
__device__ __forceinline__ void cp16g(uint32_t d, const void* s){
  asm volatile("cp.async.cg.shared.global [%0], [%1], 16;" :: "r"(d), "l"(s));
}
__device__ __forceinline__ void cp16zg(uint32_t d, const void* s, int pred){
  asm volatile("{\n .reg .pred p;\n setp.ne.b32 p, %2, 0;\n"
    " @p  cp.async.cg.shared.global [%0], [%1], 16;\n"
    " @!p cp.async.cg.shared.global [%0], [%1], 16, 0;\n}"
    :: "r"(d), "l"(s), "r"(pred));
}
#define CP_COMMIT() asm volatile("cp.async.commit_group;" ::: "memory")
#define CP_WAIT0()  asm volatile("cp.async.wait_group 0;" ::: "memory")
#define CP_WAIT1()  asm volatile("cp.async.wait_group 1;" ::: "memory")

__device__ __forceinline__ uint32_t pack2(float a, float b){
  __half2 t = __floats2half2_rn(a, b);
  return *(uint32_t*)&t;
}
__device__ __forceinline__ float tanh_ap(float x){
  float r;
  asm("tanh.approx.f32 %0, %1;" : "=f"(r) : "f"(x));
  return r;
}
__device__ __forceinline__ int ld_acq(const int* p){
  int v;
  asm volatile("ld.acquire.gpu.global.b32 %0, [%1];" : "=r"(v) : "l"(p) : "memory");
  return v;
}
__device__ __forceinline__ void red_rel(int* p){
  asm volatile("red.release.gpu.global.add.s32 [%0], %1;" :: "l"(p), "r"(1) : "memory");
}

// ---------------- merged prep (weights + embed + misc in one launch) -------------
#define PREPW_CTAS 4832
#define EMBED_CTAS (NTOK/4)

__global__ void prep_all_kernel(const int* __restrict__ wf,
                                const float* __restrict__ emb,
                                const float* __restrict__ conv_w,
                                const float* __restrict__ res_w,
                                const float* __restrict__ skip_w,
                                const float* __restrict__ w0,
                                const float* __restrict__ w1,
                                const float* __restrict__ skip_b){
  int blk = blockIdx.x;
  if (blk < PREPW_CTAS){
    int idx = blk*256 + threadIdx.x;
    if (idx < NL*128*128){
      int k = idx & 127, f = (idx>>7)&127, l = idx>>14;
      float v = (k < 64) ? conv_w[((l*2+1)*64 + k)*128 + f]
                         : conv_w[((l*2+0)*64 + (k-64))*128 + f];
      g_convw[((size_t)l*128 + f)*128 + k] = __float2half(v);
      return;
    }
    idx -= NL*128*128;
    if (idx < NL*64*64){
      int k = idx & 63, o = (idx>>6)&63, l = idx>>12;
      g_resw[((size_t)l*64 + o)*64 + k] = __float2half(res_w[((size_t)l*64 + k)*64 + o]);
      return;
    }
    idx -= NL*64*64;
    if (idx < NL*256*64){
      int k = idx & 63, v2 = (idx>>6)&255, l = idx>>14;
      g_skipw[((size_t)l*256 + v2)*64 + k] = __float2half(skip_w[((size_t)l*64 + k)*256 + v2]);
      return;
    }
    idx -= NL*256*64;
    if (idx < 256*256){
      int k = idx & 255, v2 = idx>>8;
      g_w0t[v2*256 + k] = __float2half(w0[k*256 + v2]);
      return;
    }
    idx -= 256*256;
    if (idx < 256*256){
      int k = idx & 255, v2 = idx>>8;
      g_w1t[v2*256 + k] = __float2half(w1[k*256 + v2]);
    }
    return;
  }
  blk -= PREPW_CTAS;
  if (blk < EMBED_CTAS){
    int tid = threadIdx.x;
    int tok = blk*4 + (tid >> 6);
    int c   = tid & 63;
    int t   = tok & (NT-1);
    int lab = (t == 0) ? 128 : wf[tok-1];
    g_xh[(size_t)tok*NC + c] = __float2half(emb[lab*NC + c]);
    return;
  }
  int s = threadIdx.x;
  if (s < 256){
    float a = 0.f;
    #pragma unroll 6
    for (int l = 0; l < NL; l++) a += skip_b[l*NS + s];
    g_skipb[s] = a;
    g_flags[s] = 0;
    if (s == 0){ g_num = 0.f; g_cnt = 0; }
  }
}

// ---------------- fused 30-layer kernel (R12) -------------------------------------
#define LOFF_A  1536
#define LOFF_W  36352
#define LOFF_R  71168
#define LOFF_G  80384
#define LSMEM   98816
#define APITCH  272
#define RPITCH  144

__device__ __forceinline__ void stage_w(uint32_t sbase, int l, int buf, int tid,
                                        const float* conv_b, const float* res_b){
  if (tid < 32) cp16(sbase + buf*768 + tid*16, (const char*)(conv_b + l*128) + tid*16);
  else if (tid < 48) cp16(sbase + buf*768 + 512 + (tid-32)*16,
                          (const char*)(res_b + l*64) + (tid-32)*16);
  const char* wsrc = (const char*)(g_convw + (size_t)l*16384);
  #pragma unroll
  for (int i = 0; i < 8; i++){
    int idx = tid + i*256, row = idx >> 4, c = idx & 15;
    cp16(sbase + LOFF_W + row*APITCH + c*16, wsrc + row*256 + c*16);
  }
}

__device__ __forceinline__ void stage_r(uint32_t sbase, int l, int tid){
  const char* rsrc = (const char*)(g_resw + (size_t)l*4096);
  #pragma unroll
  for (int i = 0; i < 2; i++){
    int idx = tid + i*256, row = idx >> 3, c = idx & 7;
    cp16(sbase + LOFF_R + row*RPITCH + c*16, rsrc + row*128 + c*16);
  }
}

__device__ __forceinline__ void stage_ashift(uint32_t sbase, const __half* xsrc,
                                             int dL, int tok0, int tid){
  #pragma unroll
  for (int i = 0; i < 4; i++){
    int idx = tid + i*256;
    int row = idx >> 3, c = idx & 7;
    int tok = tok0 + row, t = tok & (NT-1);
    cp16zg(sbase + LOFF_A + row*APITCH + 128 + c*16,
           (const char*)(xsrc + (long)(tok - dL)*64) + c*16, t >= dL);
  }
}

__global__ __launch_bounds__(256, 2) void layers_kernel(
    const float* __restrict__ conv_b, const float* __restrict__ res_b)
{
  extern __shared__ char sm[];
  uint32_t sbase = s2u(sm);
  const int tid = threadIdx.x, warp = tid >> 5, lane = tid & 31;
  const int l4 = lane >> 2, q = lane & 3;
  const int cta = blockIdx.x;
  const int tok0 = cta * 128;

  stage_w(sbase, 0, 0, tid, conv_b, res_b);
  stage_r(sbase, 0, tid);
  {
    const char* xs = (const char*)(g_xh + (size_t)tok0*64);
    #pragma unroll
    for (int i = 0; i < 4; i++){
      int idx = tid + i*256, row = idx >> 3, c = idx & 7;
      cp16g(sbase + LOFF_A + row*APITCH + c*16, xs + row*128 + c*16);
    }
    #pragma unroll
    for (int i = 0; i < 4; i++){
      int idx = tid + i*256, row = idx >> 3, c = idx & 7;
      int tok = tok0 + row, t = tok & (NT-1);
      cp16zg(sbase + LOFF_A + row*APITCH + 128 + c*16,
             (const char*)(g_xh + (long)(tok - 1)*64) + c*16, t >= 1);
    }
  }
  CP_COMMIT();

  const uint32_t aAddr = sbase + LOFF_A + (warp*16 + (lane & 15))*APITCH + ((lane >> 4) << 4);
  const uint32_t bAddr = sbase + LOFF_W + ((lane & 7) + ((lane >> 4) << 3))*APITCH
                       + (((lane >> 3) & 1) << 4);
  const uint32_t rAddr = sbase + LOFF_R + ((lane & 7) + ((lane >> 4) << 3))*RPITCH
                       + (((lane >> 3) & 1) << 4);

  for (int l = 0; l < NL; l++){
    const int buf = l & 1;
    CP_WAIT0();
    __syncthreads();

    uint32_t hacc[16][2];
    #pragma unroll
    for (int j = 0; j < 16; j++){ hacc[j][0]=0; hacc[j][1]=0; }
    #pragma unroll
    for (int s = 0; s < 8; s++){
      uint32_t A[4];
      ldsm4(A, aAddr + s*32);
      #pragma unroll
      for (int p = 0; p < 8; p++){
        uint32_t Bv[4];
        ldsm4(Bv, bAddr + p*16*APITCH + s*32);
        mma16816h(hacc[2*p],   A[0], A[1], A[2], A[3], Bv[0], Bv[1]);
        mma16816h(hacc[2*p+1], A[0], A[1], A[2], A[3], Bv[2], Bv[3]);
      }
    }

    const float* sCB = (const float*)(sm + buf*768);
    uint32_t G[8][2];
    #pragma unroll
    for (int j = 0; j < 8; j++){
      int c0 = j*8 + q*2;
      float b1c = sCB[c0], b2c = sCB[c0+1], b1s = sCB[64+c0], b2s = sCB[64+c0+1];
      #pragma unroll
      for (int r = 0; r < 2; r++){
        float2 f1 = __half22float2(*(__half2*)&hacc[j][r]);
        float2 f2 = __half22float2(*(__half2*)&hacc[j+8][r]);
        float h1a = f1.x + b1c;
        float h1b = f1.y + b2c;
        float h2a = f2.x + b1s;
        float h2b = f2.y + b2s;
        float ga = tanh_ap(h1a) * fmaf(0.5f, tanh_ap(0.5f*h2a), 0.5f);
        float gb = tanh_ap(h1b) * fmaf(0.5f, tanh_ap(0.5f*h2b), 0.5f);
        G[j][r] = pack2(ga, gb);
      }
    }

    float r2[8][4];
    #pragma unroll
    for (int j = 0; j < 8; j++){ r2[j][0]=0; r2[j][1]=0; r2[j][2]=0; r2[j][3]=0; }
    #pragma unroll
    for (int s = 0; s < 4; s++){
      uint32_t a0 = G[2*s][0], a1 = G[2*s][1], a2 = G[2*s+1][0], a3 = G[2*s+1][1];
      #pragma unroll
      for (int p = 0; p < 4; p++){
        uint32_t Bv[4];
        ldsm4(Bv, rAddr + p*16*RPITCH + s*32);
        mma16816(r2[2*p],   a0, a1, a2, a3, Bv[0], Bv[1]);
        mma16816(r2[2*p+1], a0, a1, a2, a3, Bv[2], Bv[3]);
      }
    }

    {
      const float* sRB = (const float*)(sm + buf*768 + 512);
      char* aRow = sm + LOFF_A + (warp*16)*APITCH;
      char* gRow = sm + LOFF_G + (warp*16)*RPITCH;
      #pragma unroll
      for (int j = 0; j < 8; j++){
        int c0 = j*8 + q*2;
        float rb0 = sRB[c0], rb1 = sRB[c0+1];
        #pragma unroll
        for (int r = 0; r < 2; r++){
          int row = l4 + 8*r;
          uint32_t xp = *(const uint32_t*)(aRow + row*APITCH + j*16 + q*4);
          float2 xb = __half22float2(*(__half2*)&xp);
          float o0 = xb.x + r2[j][2*r]   + rb0;
          float o1 = xb.y + r2[j][2*r+1] + rb1;
          *(uint32_t*)(aRow + row*APITCH + j*16 + q*4) = pack2(o0, o1);
          *(uint32_t*)(gRow + row*RPITCH + j*16 + q*4) = G[j][r];
        }
      }
    }
    __syncthreads();

    {
      char* gd = (char*)(g_gates + ((size_t)l*NTOK + tok0)*64);
      #pragma unroll
      for (int i = 0; i < 4; i++){
        int idx = tid + i*256, row = idx >> 3, c = idx & 7;
        *(uint4*)(gd + row*128 + c*16) = *(uint4*)(sm + LOFF_G + row*RPITCH + c*16);
      }
    }
    if (l < NL-1){
      char* xo = (char*)(g_xh + (size_t)(l+1)*NTOK*NC + (size_t)tok0*NC);
      #pragma unroll
      for (int i = 0; i < 4; i++){
        int idx = tid + i*256, row = idx >> 3, c = idx & 7;
        *(uint4*)(xo + row*128 + c*16) = *(uint4*)(sm + LOFF_A + row*APITCH + c*16);
      }
      stage_w(sbase, l+1, buf ^ 1, tid, conv_b, res_b);
      CP_COMMIT();
      __syncthreads();

      if (tid == 0) red_rel(g_flags + cta);
      {
        const int dnext = 1 << ((l+1) % 10);
        if (tid == 0){
          int step = dnext >> 7; if (step == 0) step = 1;
          int nb = cta - step;
          if (nb >= 0){
            while (ld_acq(g_flags + nb) < l + 1) __nanosleep(32);
          }
        }
        __syncthreads();
        stage_ashift(sbase, g_xh + (size_t)(l+1)*NTOK*NC, dnext, tok0, tid);
        stage_r(sbase, l+1, tid);
        CP_COMMIT();
      }
    }
  }
}

// ---------------- head kernel (R12: 3-slot ring + pipelined phases 2/3) -----------
#define HOFF_SKB 0
#define HOFF_B0  1024
#define HOFF_B1  2048
#define HRING    3072
#define HSTAGE   55296      /* G 18432 + WC 36864 */
#define HW2A     3072
#define HW2B     72704
#define HSMEM    168960
#define WPITCH2  272

__device__ __forceinline__ void head_stage1(uint32_t sbase, int slot, int l,
                                            int tok0, int tid){
  uint32_t gOff = HRING + slot*HSTAGE;
  uint32_t wOff = gOff + 18432;
  const char* gs = (const char*)(g_gates + ((size_t)l*NTOK + tok0)*64);
  #pragma unroll
  for (int i = 0; i < 4; i++){
    int idx = tid + i*256, row = idx >> 3, c = idx & 7;
    cp16(sbase + gOff + row*RPITCH + c*16, gs + row*128 + c*16);
  }
  const char* ws = (const char*)(g_skipw + (size_t)l*16384);
  #pragma unroll
  for (int i = 0; i < 8; i++){
    int idx = tid + i*256, row = idx >> 3, c = idx & 7;
    cp16(sbase + wOff + row*RPITCH + c*16, ws + row*128 + c*16);
  }
  CP_COMMIT();
}

__device__ __forceinline__ void stage_w2(uint32_t sbase, uint32_t bufOff,
                                         const __half* src, int kc, int tid){
  const char* ws = (const char*)src;
  #pragma unroll
  for (int i = 0; i < 16; i++){
    int idx = tid + i*256, row = idx >> 4, c = idx & 15;
    cp16(sbase + bufOff + row*WPITCH2 + c*16, ws + row*512 + kc*256 + c*16);
  }
  CP_COMMIT();
}

__device__ __forceinline__ void mma_chunk256(float acc[32][4], const uint32_t P[32][2],
                                             uint32_t wbase, int kc, uint32_t bLane2){
  #pragma unroll
  for (int s = 0; s < 8; s++){
    int S = kc*8 + s;
    uint32_t a0 = P[2*S][0], a1 = P[2*S][1], a2 = P[2*S+1][0], a3 = P[2*S+1][1];
    #pragma unroll
    for (int p = 0; p < 16; p++){
      uint32_t Bv[4];
      ldsm4(Bv, wbase + bLane2 + p*16*WPITCH2 + s*32);
      mma16816(acc[2*p],   a0, a1, a2, a3, Bv[0], Bv[1]);
      mma16816(acc[2*p+1], a0, a1, a2, a3, Bv[2], Bv[3]);
    }
  }
}

__global__ __launch_bounds__(256, 1) void head_kernel(
    const float* __restrict__ b0, const float* __restrict__ b1,
    const int* __restrict__ wf, const int* __restrict__ lens,
    float* __restrict__ out)
{
  extern __shared__ char sm[];
  uint32_t sbase = s2u(sm);
  const int tid = threadIdx.x, warp = tid >> 5, lane = tid & 31;
  const int l4 = lane >> 2, q = lane & 3;
  const int tok0 = blockIdx.x * 128;

  float* sSKB = (float*)(sm + HOFF_SKB);
  float* sB0  = (float*)(sm + HOFF_B0);
  float* sB1  = (float*)(sm + HOFF_B1);
  sSKB[tid] = g_skipb[tid];
  sB0[tid]  = b0[tid];
  sB1[tid]  = b1[tid];

  head_stage1(sbase, 0, 0, tok0, tid);
  head_stage1(sbase, 1, 1, tok0, tid);

  float acc[32][4];
  #pragma unroll
  for (int j = 0; j < 32; j++){ acc[j][0]=0; acc[j][1]=0; acc[j][2]=0; acc[j][3]=0; }

  const uint32_t aLane = (warp*16 + (lane & 15))*RPITCH + ((lane >> 4) << 4);
  const uint32_t bLane = ((lane & 7) + ((lane >> 4) << 3))*RPITCH + (((lane >> 3) & 1) << 4);
  const uint32_t bLane2 = ((lane & 7) + ((lane >> 4) << 3))*WPITCH2 + (((lane >> 3) & 1) << 4);

  for (int l = 0; l < NL; l++){
    const int slot = l % 3;
    if (l < NL-1) CP_WAIT1(); else CP_WAIT0();
    __syncthreads();

    if (l == NL-1){
      stage_w2(sbase, HW2A, g_w0t, 0, tid);
    }

    uint32_t aAddr = sbase + HRING + slot*HSTAGE + aLane;
    uint32_t bAddr = sbase + HRING + slot*HSTAGE + 18432 + bLane;
    #pragma unroll
    for (int s = 0; s < 4; s++){
      uint32_t A[4];
      ldsm4(A, aAddr + s*32);
      #pragma unroll
      for (int p = 0; p < 16; p++){
        uint32_t Bv[4];
        ldsm4(Bv, bAddr + p*16*RPITCH + s*32);
        mma16816(acc[2*p],   A[0], A[1], A[2], A[3], Bv[0], Bv[1]);
        mma16816(acc[2*p+1], A[0], A[1], A[2], A[3], Bv[2], Bv[3]);
      }
    }
    if (l + 2 < NL)
      head_stage1(sbase, (l+2)%3, l+2, tok0, tid);
  }

  uint32_t P[32][2];
  #pragma unroll
  for (int j = 0; j < 32; j++){
    int c0 = j*8 + q*2;
    float s0 = sSKB[c0], s1 = sSKB[c0+1];
    P[j][0] = pack2(acc[j][0] + s0, acc[j][1] + s1);
    P[j][1] = pack2(acc[j][2] + s0, acc[j][3] + s1);
  }

  #pragma unroll
  for (int j = 0; j < 32; j++){ acc[j][0]=0; acc[j][1]=0; acc[j][2]=0; acc[j][3]=0; }
  CP_WAIT0(); __syncthreads();
  stage_w2(sbase, HW2B, g_w0t, 1, tid);
  mma_chunk256(acc, P, sbase + HW2A, 0, bLane2);
  CP_WAIT0(); __syncthreads();
  stage_w2(sbase, HW2A, g_w1t, 0, tid);
  mma_chunk256(acc, P, sbase + HW2B, 1, bLane2);
  CP_WAIT0(); __syncthreads();
  stage_w2(sbase, HW2B, g_w1t, 1, tid);

  #pragma unroll
  for (int j = 0; j < 32; j++){
    int c0 = j*8 + q*2;
    float s0 = sB0[c0], s1 = sB0[c0+1];
    P[j][0] = pack2(fmaxf(acc[j][0] + s0, 0.f), fmaxf(acc[j][1] + s1, 0.f));
    P[j][1] = pack2(fmaxf(acc[j][2] + s0, 0.f), fmaxf(acc[j][3] + s1, 0.f));
  }

  #pragma unroll
  for (int j = 0; j < 32; j++){ acc[j][0]=0; acc[j][1]=0; acc[j][2]=0; acc[j][3]=0; }
  mma_chunk256(acc, P, sbase + HW2A, 0, bLane2);
  CP_WAIT0(); __syncthreads();
  mma_chunk256(acc, P, sbase + HW2B, 1, bLane2);

  float local = 0.f;
  int tokA = tok0 + warp*16 + l4;
  #pragma unroll
  for (int r = 0; r < 2; r++){
    int tok = tokA + r*8;
    int lab = wf[tok];
    float m = -1e30f;
    #pragma unroll
    for (int j = 0; j < 32; j++){
      int c0 = j*8 + q*2;
      float v0 = acc[j][2*r]   + sB1[c0];
      float v1 = acc[j][2*r+1] + sB1[c0+1];
      m = fmaxf(m, fmaxf(v0, v1));
    }
    m = fmaxf(m, __shfl_xor_sync(0xffffffffu, m, 1));
    m = fmaxf(m, __shfl_xor_sync(0xffffffffu, m, 2));
    float s = 0.f, lv = 0.f;
    #pragma unroll
    for (int j = 0; j < 32; j++){
      int c0 = j*8 + q*2;
      float v0 = acc[j][2*r]   + sB1[c0];
      float v1 = acc[j][2*r+1] + sB1[c0+1];
      s += __expf(v0 - m) + __expf(v1 - m);
      if (lab == c0)   lv += v0;
      if (lab == c0+1) lv += v1;
    }
    s  += __shfl_xor_sync(0xffffffffu, s, 1);
    s  += __shfl_xor_sync(0xffffffffu, s, 2);
    lv += __shfl_xor_sync(0xffffffffu, lv, 1);
    lv += __shfl_xor_sync(0xffffffffu, lv, 2);
    float ce = m + logf(s) - lv;
    int t = tok & (NT-1);
    int b = tok >> 13;
    if (q == 0 && t < lens[b]) local += ce;
  }
  #pragma unroll
  for (int off = 16; off; off >>= 1)
    local += __shfl_xor_sync(0xffffffffu, local, off);
  if (lane == 0) atomicAdd(&g_num, local);

  __syncthreads();
  if (tid == 0){
    __threadfence();
    if (atomicAdd(&g_cnt, 1) == gridDim.x - 1){
      float num = atomicAdd(&g_num, 0.f);
      float denom = 0.f;
      for (int b = 0; b < NB; b++) denom += (float)lens[b];
      out[0] = num / fmaxf(denom, 1.f);
    }
  }
}

// ---------------- launcher ----------------------------------------------------------
extern "C" void kernel_launch(void* const* d_in, const int* in_sizes, int n_in,
                              void* d_out, int out_size)
{
  const int*   wf     = (const int*)d_in[0];
  const int*   lens   = (const int*)d_in[1];
  const float* emb    = (const float*)d_in[2];
  const float* conv_w = (const float*)d_in[3];
  const float* conv_b = (const float*)d_in[4];
  const float* res_w  = (const float*)d_in[5];
  const float* res_b  = (const float*)d_in[6];
  const float* skip_w = (const float*)d_in[7];
  const float* skip_b = (const float*)d_in[8];
  const float* w0     = (const float*)d_in[9];
  const float* b0     = (const float*)d_in[10];
  const float* w1     = (const float*)d_in[11];
  const float* b1     = (const float*)d_in[12];

  cudaFuncSetAttribute(layers_kernel, cudaFuncAttributeMaxDynamicSharedMemorySize, LSMEM);
  cudaFuncSetAttribute(head_kernel,   cudaFuncAttributeMaxDynamicSharedMemorySize, HSMEM);

  prep_all_kernel<<<PREPW_CTAS + EMBED_CTAS + 1, 256>>>(wf, emb, conv_w, res_w,
                                                        skip_w, w0, w1, skip_b);
  layers_kernel<<<NTOK/128, 256, LSMEM>>>(conv_b, res_b);
  head_kernel<<<NTOK/128, 256, HSMEM>>>(b0, b1, wf, lens, (float*)d_out);
}

// round 16
// speedup vs baseline: 1.1709x; 1.0062x over previous
#include <cuda_runtime.h>
#include <cuda_fp16.h>
#include <math.h>
#include <stdint.h>

#define NB 4
#define NT 8192
#define NC 64
#define NS 256
#define NV 256
#define NL 30
#define NTOK (NB*NT)

// ---------------- device scratch ---------------------------------------------
__device__ __half g_xh[(size_t)(NL+1)*NTOK*NC];
__device__ __half g_gates[(size_t)NL*NTOK*NC];   // [l][tok][64]
__device__ __half g_convw[NL*128*128];
__device__ __half g_resw[NL*64*64];
__device__ __half g_skipw[NL*256*64];
__device__ __half g_w0t[256*256];
__device__ __half g_w1t[256*256];
__device__ __half g_cbh[NL*128];                 // conv bias as half
__device__ float g_skipb[NS];
__device__ float g_num;
__device__ int   g_cnt;
__device__ int   g_flags[256];

// ---------------- helpers ------------------------------------------------------
__device__ __forceinline__ uint32_t s2u(const void* p){
  uint32_t a;
  asm("{ .reg .u64 t; cvta.to.shared.u64 t, %1; cvt.u32.u64 %0, t; }" : "=r"(a) : "l"(p));
  return a;
}
__device__ __forceinline__ void mma16816(float* c, uint32_t a0, uint32_t a1,
                                         uint32_t a2, uint32_t a3,
                                         uint32_t b0, uint32_t b1){
  asm volatile("mma.sync.aligned.m16n8k16.row.col.f32.f16.f16.f32 "
    "{%0,%1,%2,%3}, {%4,%5,%6,%7}, {%8,%9}, {%0,%1,%2,%3};"
    : "+f"(c[0]), "+f"(c[1]), "+f"(c[2]), "+f"(c[3])
    : "r"(a0), "r"(a1), "r"(a2), "r"(a3), "r"(b0), "r"(b1));
}
__device__ __forceinline__ void mma16816h(uint32_t* c, uint32_t a0, uint32_t a1,
                                          uint32_t a2, uint32_t a3,
                                          uint32_t b0, uint32_t b1){
  asm volatile("mma.sync.aligned.m16n8k16.row.col.f16.f16.f16.f16 "
    "{%0,%1}, {%2,%3,%4,%5}, {%6,%7}, {%0,%1};"
    : "+r"(c[0]), "+r"(c[1])
    : "r"(a0), "r"(a1), "r"(a2), "r"(a3), "r"(b0), "r"(b1));
}
__device__ __forceinline__ void ldsm4(uint32_t* r, uint32_t a){
  asm volatile("ldmatrix.sync.aligned.m8n8.x4.shared.b16 {%0,%1,%2,%3}, [%4];"
    : "=r"(r[0]), "=r"(r[1]), "=r"(r[2]), "=r"(r[3]) : "r"(a));
}
__device__ __forceinline__ void cp16(uint32_t d, const void* s){
  asm volatile("cp.async.ca.shared.global [%0], [%1], 16;" :: "r"(d), "l"(s));
}
__device__ __forceinline__ void cp16g(uint32_t d, const void* s){
  asm volatile("cp.async.cg.shared.global [%0], [%1], 16;" :: "r"(d), "l"(s));
}
__device__ __forceinline__ void cp16zg(uint32_t d, const void* s, int pred){
  asm volatile("{\n .reg .pred p;\n setp.ne.b32 p, %2, 0;\n"
    " @p  cp.async.cg.shared.global [%0], [%1], 16;\n"
    " @!p cp.async.cg.shared.global [%0], [%1], 16, 0;\n}"
    :: "r"(d), "l"(s), "r"(pred));
}
#define CP_COMMIT() asm volatile("cp.async.commit_group;" ::: "memory")
#define CP_WAIT0()  asm volatile("cp.async.wait_group 0;" ::: "memory")
#define CP_WAIT1()  asm volatile("cp.async.wait_group 1;" ::: "memory")

__device__ __forceinline__ uint32_t pack2(float a, float b){
  __half2 t = __floats2half2_rn(a, b);
  return *(uint32_t*)&t;
}
__device__ __forceinline__ uint32_t h2tanh(uint32_t x){
  uint32_t r;
  asm("tanh.approx.f16x2 %0, %1;" : "=r"(r) : "r"(x));
  return r;
}
__device__ __forceinline__ int ld_acq(const int* p){
  int v;
  asm volatile("ld.acquire.gpu.global.b32 %0, [%1];" : "=r"(v) : "l"(p) : "memory");
  return v;
}
__device__ __forceinline__ void red_rel(int* p){
  asm volatile("red.release.gpu.global.add.s32 [%0], %1;" :: "l"(p), "r"(1) : "memory");
}

// ---------------- merged prep (weights + embed + misc in one launch) -------------
#define PREPW_CTAS 4832
#define EMBED_CTAS (NTOK/4)

__global__ void prep_all_kernel(const int* __restrict__ wf,
                                const float* __restrict__ emb,
                                const float* __restrict__ conv_w,
                                const float* __restrict__ conv_b,
                                const float* __restrict__ res_w,
                                const float* __restrict__ skip_w,
                                const float* __restrict__ w0,
                                const float* __restrict__ w1,
                                const float* __restrict__ skip_b){
  int blk = blockIdx.x;
  if (blk < PREPW_CTAS){
    int idx = blk*256 + threadIdx.x;
    if (idx < NL*128*128){
      int k = idx & 127, f = (idx>>7)&127, l = idx>>14;
      float v = (k < 64) ? conv_w[((l*2+1)*64 + k)*128 + f]
                         : conv_w[((l*2+0)*64 + (k-64))*128 + f];
      g_convw[((size_t)l*128 + f)*128 + k] = __float2half(v);
      return;
    }
    idx -= NL*128*128;
    if (idx < NL*64*64){
      int k = idx & 63, o = (idx>>6)&63, l = idx>>12;
      g_resw[((size_t)l*64 + o)*64 + k] = __float2half(res_w[((size_t)l*64 + k)*64 + o]);
      return;
    }
    idx -= NL*64*64;
    if (idx < NL*256*64){
      int k = idx & 63, v2 = (idx>>6)&255, l = idx>>14;
      g_skipw[((size_t)l*256 + v2)*64 + k] = __float2half(skip_w[((size_t)l*64 + k)*256 + v2]);
      return;
    }
    idx -= NL*256*64;
    if (idx < 256*256){
      int k = idx & 255, v2 = idx>>8;
      g_w0t[v2*256 + k] = __float2half(w0[k*256 + v2]);
      return;
    }
    idx -= 256*256;
    if (idx < 256*256){
      int k = idx & 255, v2 = idx>>8;
      g_w1t[v2*256 + k] = __float2half(w1[k*256 + v2]);
    }
    return;
  }
  blk -= PREPW_CTAS;
  if (blk < EMBED_CTAS){
    int tid = threadIdx.x;
    int tok = blk*4 + (tid >> 6);
    int c   = tid & 63;
    int t   = tok & (NT-1);
    int lab = (t == 0) ? 128 : wf[tok-1];
    g_xh[(size_t)tok*NC + c] = __float2half(emb[lab*NC + c]);
    return;
  }
  int s = threadIdx.x;
  if (s < 256){
    float a = 0.f;
    #pragma unroll 6
    for (int l = 0; l < NL; l++) a += skip_b[l*NS + s];
    g_skipb[s] = a;
    g_flags[s] = 0;
    if (s == 0){ g_num = 0.f; g_cnt = 0; }
    for (int i = s; i < NL*128; i += 256)
      g_cbh[i] = __float2half(conv_b[i]);
  }
}

// ---------------- fused 30-layer kernel -------------------------------------------
#define LOFF_A  1536
#define LOFF_W  36352
#define LOFF_R  71168
#define LOFF_G  80384
#define LSMEM   98816
#define APITCH  272
#define RPITCH  144

__device__ __forceinline__ void stage_w(uint32_t sbase, int l, int buf, int tid,
                                        const float* res_b){
  if (tid < 16) cp16(sbase + buf*768 + tid*16, (const char*)(g_cbh + l*128) + tid*16);
  else if (tid >= 32 && tid < 48)
    cp16(sbase + buf*768 + 512 + (tid-32)*16, (const char*)(res_b + l*64) + (tid-32)*16);
  const char* wsrc = (const char*)(g_convw + (size_t)l*16384);
  #pragma unroll
  for (int i = 0; i < 8; i++){
    int idx = tid + i*256, row = idx >> 4, c = idx & 15;
    cp16(sbase + LOFF_W + row*APITCH + c*16, wsrc + row*256 + c*16);
  }
}

__device__ __forceinline__ void stage_r(uint32_t sbase, int l, int tid){
  const char* rsrc = (const char*)(g_resw + (size_t)l*4096);
  #pragma unroll
  for (int i = 0; i < 2; i++){
    int idx = tid + i*256, row = idx >> 3, c = idx & 7;
    cp16(sbase + LOFF_R + row*RPITCH + c*16, rsrc + row*128 + c*16);
  }
}

__device__ __forceinline__ void stage_ashift(uint32_t sbase, const __half* xsrc,
                                             int dL, int tok0, int tid){
  #pragma unroll
  for (int i = 0; i < 4; i++){
    int idx = tid + i*256;
    int row = idx >> 3, c = idx & 7;
    int tok = tok0 + row, t = tok & (NT-1);
    cp16zg(sbase + LOFF_A + row*APITCH + 128 + c*16,
           (const char*)(xsrc + (long)(tok - dL)*64) + c*16, t >= dL);
  }
}

__global__ __launch_bounds__(256, 2) void layers_kernel(const float* __restrict__ res_b)
{
  extern __shared__ char sm[];
  uint32_t sbase = s2u(sm);
  const int tid = threadIdx.x, warp = tid >> 5, lane = tid & 31;
  const int l4 = lane >> 2, q = lane & 3;
  const int cta = blockIdx.x;
  const int tok0 = cta * 128;

  stage_w(sbase, 0, 0, tid, res_b);
  stage_r(sbase, 0, tid);
  {
    const char* xs = (const char*)(g_xh + (size_t)tok0*64);
    #pragma unroll
    for (int i = 0; i < 4; i++){
      int idx = tid + i*256, row = idx >> 3, c = idx & 7;
      cp16g(sbase + LOFF_A + row*APITCH + c*16, xs + row*128 + c*16);
    }
    #pragma unroll
    for (int i = 0; i < 4; i++){
      int idx = tid + i*256, row = idx >> 3, c = idx & 7;
      int tok = tok0 + row, t = tok & (NT-1);
      cp16zg(sbase + LOFF_A + row*APITCH + 128 + c*16,
             (const char*)(g_xh + (long)(tok - 1)*64) + c*16, t >= 1);
    }
  }
  CP_COMMIT();

  const uint32_t aAddr = sbase + LOFF_A + (warp*16 + (lane & 15))*APITCH + ((lane >> 4) << 4);
  const uint32_t bAddr = sbase + LOFF_W + ((lane & 7) + ((lane >> 4) << 3))*APITCH
                       + (((lane >> 3) & 1) << 4);
  const uint32_t rAddr = sbase + LOFF_R + ((lane & 7) + ((lane >> 4) << 3))*RPITCH
                       + (((lane >> 3) & 1) << 4);

  const __half2 half05 = __float2half2_rn(0.5f);

  for (int l = 0; l < NL; l++){
    const int buf = l & 1;
    CP_WAIT0();
    __syncthreads();

    // ---- conv GEMM (f16 accum) ----
    uint32_t hacc[16][2];
    #pragma unroll
    for (int j = 0; j < 16; j++){ hacc[j][0]=0; hacc[j][1]=0; }
    #pragma unroll
    for (int s = 0; s < 8; s++){
      uint32_t A[4];
      ldsm4(A, aAddr + s*32);
      #pragma unroll
      for (int p = 0; p < 8; p++){
        uint32_t Bv[4];
        ldsm4(Bv, bAddr + p*16*APITCH + s*32);
        mma16816h(hacc[2*p],   A[0], A[1], A[2], A[3], Bv[0], Bv[1]);
        mma16816h(hacc[2*p+1], A[0], A[1], A[2], A[3], Bv[2], Bv[3]);
      }
    }

    // ---- gate: fully f16x2 (tanh.approx.f16x2, 2 MUFU per channel pair) ----
    const uint32_t* cbh = (const uint32_t*)(sm + buf*768);
    uint32_t G[8][2];
    #pragma unroll
    for (int j = 0; j < 8; j++){
      uint32_t cb1 = cbh[j*4 + q];
      uint32_t cb2 = cbh[32 + j*4 + q];
      #pragma unroll
      for (int r = 0; r < 2; r++){
        __half2 h1 = __hadd2(*(__half2*)&hacc[j][r],   *(__half2*)&cb1);
        __half2 h2 = __hadd2(*(__half2*)&hacc[j+8][r], *(__half2*)&cb2);
        uint32_t t1 = h2tanh(*(uint32_t*)&h1);
        __half2 h2h = __hmul2(h2, half05);
        uint32_t t2 = h2tanh(*(uint32_t*)&h2h);
        __half2 sg = __hfma2(*(__half2*)&t2, half05, half05);
        __half2 gv = __hmul2(*(__half2*)&t1, sg);
        G[j][r] = *(uint32_t*)&gv;
      }
    }

    // ---- residual GEMM (f16 in, f32 accum) ----
    float r2[8][4];
    #pragma unroll
    for (int j = 0; j < 8; j++){ r2[j][0]=0; r2[j][1]=0; r2[j][2]=0; r2[j][3]=0; }
    #pragma unroll
    for (int s = 0; s < 4; s++){
      uint32_t a0 = G[2*s][0], a1 = G[2*s][1], a2 = G[2*s+1][0], a3 = G[2*s+1][1];
      #pragma unroll
      for (int p = 0; p < 4; p++){
        uint32_t Bv[4];
        ldsm4(Bv, rAddr + p*16*RPITCH + s*32);
        mma16816(r2[2*p],   a0, a1, a2, a3, Bv[0], Bv[1]);
        mma16816(r2[2*p+1], a0, a1, a2, a3, Bv[2], Bv[3]);
      }
    }

    // ---- writeback in-place into A half1 + gate STS ----
    {
      const float* sRB = (const float*)(sm + buf*768 + 512);
      char* aRow = sm + LOFF_A + (warp*16)*APITCH;
      char* gRow = sm + LOFF_G + (warp*16)*RPITCH;
      #pragma unroll
      for (int j = 0; j < 8; j++){
        int c0 = j*8 + q*2;
        float rb0 = sRB[c0], rb1 = sRB[c0+1];
        #pragma unroll
        for (int r = 0; r < 2; r++){
          int row = l4 + 8*r;
          uint32_t xp = *(const uint32_t*)(aRow + row*APITCH + j*16 + q*4);
          float2 xb = __half22float2(*(__half2*)&xp);
          float o0 = xb.x + r2[j][2*r]   + rb0;
          float o1 = xb.y + r2[j][2*r+1] + rb1;
          *(uint32_t*)(aRow + row*APITCH + j*16 + q*4) = pack2(o0, o1);
          *(uint32_t*)(gRow + row*RPITCH + j*16 + q*4) = G[j][r];
        }
      }
    }
    __syncthreads();

    {
      char* gd = (char*)(g_gates + ((size_t)l*NTOK + tok0)*64);
      #pragma unroll
      for (int i = 0; i < 4; i++){
        int idx = tid + i*256, row = idx >> 3, c = idx & 7;
        *(uint4*)(gd + row*128 + c*16) = *(uint4*)(sm + LOFF_G + row*RPITCH + c*16);
      }
    }
    if (l < NL-1){
      char* xo = (char*)(g_xh + (size_t)(l+1)*NTOK*NC + (size_t)tok0*NC);
      #pragma unroll
      for (int i = 0; i < 4; i++){
        int idx = tid + i*256, row = idx >> 3, c = idx & 7;
        *(uint4*)(xo + row*128 + c*16) = *(uint4*)(sm + LOFF_A + row*APITCH + c*16);
      }
      stage_w(sbase, l+1, buf ^ 1, tid, res_b);
      CP_COMMIT();
      __syncthreads();

      if (tid == 0) red_rel(g_flags + cta);
      {
        const int dnext = 1 << ((l+1) % 10);
        if (tid == 0){
          int step = dnext >> 7; if (step == 0) step = 1;
          int nb = cta - step;
          if (nb >= 0){
            while (ld_acq(g_flags + nb) < l + 1) __nanosleep(32);
          }
        }
        __syncthreads();
        stage_ashift(sbase, g_xh + (size_t)(l+1)*NTOK*NC, dnext, tok0, tid);
        stage_r(sbase, l+1, tid);
        CP_COMMIT();
      }
    }
  }
}

// ---------------- head kernel (R12: 3-slot ring + pipelined phases 2/3) -----------
#define HOFF_SKB 0
#define HOFF_B0  1024
#define HOFF_B1  2048
#define HRING    3072
#define HSTAGE   55296
#define HW2A     3072
#define HW2B     72704
#define HSMEM    168960
#define WPITCH2  272

__device__ __forceinline__ void head_stage1(uint32_t sbase, int slot, int l,
                                            int tok0, int tid){
  uint32_t gOff = HRING + slot*HSTAGE;
  uint32_t wOff = gOff + 18432;
  const char* gs = (const char*)(g_gates + ((size_t)l*NTOK + tok0)*64);
  #pragma unroll
  for (int i = 0; i < 4; i++){
    int idx = tid + i*256, row = idx >> 3, c = idx & 7;
    cp16(sbase + gOff + row*RPITCH + c*16, gs + row*128 + c*16);
  }
  const char* ws = (const char*)(g_skipw + (size_t)l*16384);
  #pragma unroll
  for (int i = 0; i < 8; i++){
    int idx = tid + i*256, row = idx >> 3, c = idx & 7;
    cp16(sbase + wOff + row*RPITCH + c*16, ws + row*128 + c*16);
  }
  CP_COMMIT();
}

__device__ __forceinline__ void stage_w2(uint32_t sbase, uint32_t bufOff,
                                         const __half* src, int kc, int tid){
  const char* ws = (const char*)src;
  #pragma unroll
  for (int i = 0; i < 16; i++){
    int idx = tid + i*256, row = idx >> 4, c = idx & 15;
    cp16(sbase + bufOff + row*WPITCH2 + c*16, ws + row*512 + kc*256 + c*16);
  }
  CP_COMMIT();
}

__device__ __forceinline__ void mma_chunk256(float acc[32][4], const uint32_t P[32][2],
                                             uint32_t wbase, int kc, uint32_t bLane2){
  #pragma unroll
  for (int s = 0; s < 8; s++){
    int S = kc*8 + s;
    uint32_t a0 = P[2*S][0], a1 = P[2*S][1], a2 = P[2*S+1][0], a3 = P[2*S+1][1];
    #pragma unroll
    for (int p = 0; p < 16; p++){
      uint32_t Bv[4];
      ldsm4(Bv, wbase + bLane2 + p*16*WPITCH2 + s*32);
      mma16816(acc[2*p],   a0, a1, a2, a3, Bv[0], Bv[1]);
      mma16816(acc[2*p+1], a0, a1, a2, a3, Bv[2], Bv[3]);
    }
  }
}

__global__ __launch_bounds__(256, 1) void head_kernel(
    const float* __restrict__ b0, const float* __restrict__ b1,
    const int* __restrict__ wf, const int* __restrict__ lens,
    float* __restrict__ out)
{
  extern __shared__ char sm[];
  uint32_t sbase = s2u(sm);
  const int tid = threadIdx.x, warp = tid >> 5, lane = tid & 31;
  const int l4 = lane >> 2, q = lane & 3;
  const int tok0 = blockIdx.x * 128;

  float* sSKB = (float*)(sm + HOFF_SKB);
  float* sB0  = (float*)(sm + HOFF_B0);
  float* sB1  = (float*)(sm + HOFF_B1);
  sSKB[tid] = g_skipb[tid];
  sB0[tid]  = b0[tid];
  sB1[tid]  = b1[tid];

  head_stage1(sbase, 0, 0, tok0, tid);
  head_stage1(sbase, 1, 1, tok0, tid);

  float acc[32][4];
  #pragma unroll
  for (int j = 0; j < 32; j++){ acc[j][0]=0; acc[j][1]=0; acc[j][2]=0; acc[j][3]=0; }

  const uint32_t aLane = (warp*16 + (lane & 15))*RPITCH + ((lane >> 4) << 4);
  const uint32_t bLane = ((lane & 7) + ((lane >> 4) << 3))*RPITCH + (((lane >> 3) & 1) << 4);
  const uint32_t bLane2 = ((lane & 7) + ((lane >> 4) << 3))*WPITCH2 + (((lane >> 3) & 1) << 4);

  for (int l = 0; l < NL; l++){
    const int slot = l % 3;
    if (l < NL-1) CP_WAIT1(); else CP_WAIT0();
    __syncthreads();

    if (l == NL-1){
      stage_w2(sbase, HW2A, g_w0t, 0, tid);
    }

    uint32_t aAddr = sbase + HRING + slot*HSTAGE + aLane;
    uint32_t bAddr = sbase + HRING + slot*HSTAGE + 18432 + bLane;
    #pragma unroll
    for (int s = 0; s < 4; s++){
      uint32_t A[4];
      ldsm4(A, aAddr + s*32);
      #pragma unroll
      for (int p = 0; p < 16; p++){
        uint32_t Bv[4];
        ldsm4(Bv, bAddr + p*16*RPITCH + s*32);
        mma16816(acc[2*p],   A[0], A[1], A[2], A[3], Bv[0], Bv[1]);
        mma16816(acc[2*p+1], A[0], A[1], A[2], A[3], Bv[2], Bv[3]);
      }
    }
    if (l + 2 < NL)
      head_stage1(sbase, (l+2)%3, l+2, tok0, tid);
  }

  uint32_t P[32][2];
  #pragma unroll
  for (int j = 0; j < 32; j++){
    int c0 = j*8 + q*2;
    float s0 = sSKB[c0], s1 = sSKB[c0+1];
    P[j][0] = pack2(acc[j][0] + s0, acc[j][1] + s1);
    P[j][1] = pack2(acc[j][2] + s0, acc[j][3] + s1);
  }

  #pragma unroll
  for (int j = 0; j < 32; j++){ acc[j][0]=0; acc[j][1]=0; acc[j][2]=0; acc[j][3]=0; }
  CP_WAIT0(); __syncthreads();
  stage_w2(sbase, HW2B, g_w0t, 1, tid);
  mma_chunk256(acc, P, sbase + HW2A, 0, bLane2);
  CP_WAIT0(); __syncthreads();
  stage_w2(sbase, HW2A, g_w1t, 0, tid);
  mma_chunk256(acc, P, sbase + HW2B, 1, bLane2);
  CP_WAIT0(); __syncthreads();
  stage_w2(sbase, HW2B, g_w1t, 1, tid);

  #pragma unroll
  for (int j = 0; j < 32; j++){
    int c0 = j*8 + q*2;
    float s0 = sB0[c0], s1 = sB0[c0+1];
    P[j][0] = pack2(fmaxf(acc[j][0] + s0, 0.f), fmaxf(acc[j][1] + s1, 0.f));
    P[j][1] = pack2(fmaxf(acc[j][2] + s0, 0.f), fmaxf(acc[j][3] + s1, 0.f));
  }

  #pragma unroll
  for (int j = 0; j < 32; j++){ acc[j][0]=0; acc[j][1]=0; acc[j][2]=0; acc[j][3]=0; }
  mma_chunk256(acc, P, sbase + HW2A, 0, bLane2);
  CP_WAIT0(); __syncthreads();
  mma_chunk256(acc, P, sbase + HW2B, 1, bLane2);

  float local = 0.f;
  int tokA = tok0 + warp*16 + l4;
  #pragma unroll
  for (int r = 0; r < 2; r++){
    int tok = tokA + r*8;
    int lab = wf[tok];
    float m = -1e30f;
    #pragma unroll
    for (int j = 0; j < 32; j++){
      int c0 = j*8 + q*2;
      float v0 = acc[j][2*r]   + sB1[c0];
      float v1 = acc[j][2*r+1] + sB1[c0+1];
      m = fmaxf(m, fmaxf(v0, v1));
    }
    m = fmaxf(m, __shfl_xor_sync(0xffffffffu, m, 1));
    m = fmaxf(m, __shfl_xor_sync(0xffffffffu, m, 2));
    float s = 0.f, lv = 0.f;
    #pragma unroll
    for (int j = 0; j < 32; j++){
      int c0 = j*8 + q*2;
      float v0 = acc[j][2*r]   + sB1[c0];
      float v1 = acc[j][2*r+1] + sB1[c0+1];
      s += __expf(v0 - m) + __expf(v1 - m);
      if (lab == c0)   lv += v0;
      if (lab == c0+1) lv += v1;
    }
    s  += __shfl_xor_sync(0xffffffffu, s, 1);
    s  += __shfl_xor_sync(0xffffffffu, s, 2);
    lv += __shfl_xor_sync(0xffffffffu, lv, 1);
    lv += __shfl_xor_sync(0xffffffffu, lv, 2);
    float ce = m + logf(s) - lv;
    int t = tok & (NT-1);
    int b = tok >> 13;
    if (q == 0 && t < lens[b]) local += ce;
  }
  #pragma unroll
  for (int off = 16; off; off >>= 1)
    local += __shfl_xor_sync(0xffffffffu, local, off);
  if (lane == 0) atomicAdd(&g_num, local);

  __syncthreads();
  if (tid == 0){
    __threadfence();
    if (atomicAdd(&g_cnt, 1) == gridDim.x - 1){
      float num = atomicAdd(&g_num, 0.f);
      float denom = 0.f;
      for (int b = 0; b < NB; b++) denom += (float)lens[b];
      out[0] = num / fmaxf(denom, 1.f);
    }
  }
}

// ---------------- launcher ----------------------------------------------------------
extern "C" void kernel_launch(void* const* d_in, const int* in_sizes, int n_in,
                              void* d_out, int out_size)
{
  const int*   wf     = (const int*)d_in[0];
  const int*   lens   = (const int*)d_in[1];
  const float* emb    = (const float*)d_in[2];
  const float* conv_w = (const float*)d_in[3];
  const float* conv_b = (const float*)d_in[4];
  const float* res_w  = (const float*)d_in[5];
  const float* res_b  = (const float*)d_in[6];
  const float* skip_w = (const float*)d_in[7];
  const float* skip_b = (const float*)d_in[8];
  const float* w0     = (const float*)d_in[9];
  const float* b0     = (const float*)d_in[10];
  const float* w1     = (const float*)d_in[11];
  const float* b1     = (const float*)d_in[12];

  cudaFuncSetAttribute(layers_kernel, cudaFuncAttributeMaxDynamicSharedMemorySize, LSMEM);
  cudaFuncSetAttribute(head_kernel,   cudaFuncAttributeMaxDynamicSharedMemorySize, HSMEM);

  prep_all_kernel<<<PREPW_CTAS + EMBED_CTAS + 1, 256>>>(wf, emb, conv_w, conv_b, res_w,
                                                        skip_w, w0, w1, skip_b);
  layers_kernel<<<NTOK/128, 256, LSMEM>>>(res_b);
  head_kernel<<<NTOK/128, 256, HSMEM>>>(b0, b1, wf, lens, (float*)d_out);
}